// round 10
// baseline (speedup 1.0000x reference)
#include <cuda_runtime.h>
#include <cuda_bf16.h>
#include <cuda_fp16.h>
#include <cstdint>

#define NMAX 50000
#define EMAX 800000
#define NPAD (NMAX + 128)

// ---------------- scratch ----------------
__device__ __align__(16) __nv_bfloat16 d_A1[NPAD * 128];  // GEMM input, hi plane
__device__ __align__(16) __nv_bfloat16 d_A2[NPAD * 128];  // GEMM input, lo plane
__device__ __align__(16) __half d_y16[NMAX * 128];        // aggregated-path GEMM out (fp16)
__device__ __align__(16) float  d_z[NMAX * 128];          // self-path GEMM out (fp32)
__device__ __align__(16) __nv_bfloat16 d_W1t0[256 * 128];
__device__ __align__(16) __nv_bfloat16 d_W2t0[256 * 128];
__device__ __align__(16) __nv_bfloat16 d_W1t1[256 * 128];
__device__ __align__(16) __nv_bfloat16 d_W2t1[256 * 128];
__device__ __align__(16) __nv_bfloat16 d_W1t2[128 * 128];
__device__ __align__(16) __nv_bfloat16 d_W2t2[128 * 128];
__device__ __align__(16) float d_bias0[256];
__device__ __align__(16) float d_bias1[256];
__device__ __align__(16) float d_bias2[128];
__device__ int   d_deg[NMAX];
__device__ int   d_off[NMAX];
__device__ int   d_cur[NMAX];
__device__ float d_invdeg[NMAX];
__device__ int   d_csr[EMAX];
__device__ int   d_bsum[256];
__device__ int   d_boff[256];
__device__ int   d_e64;

// ---------------- split x -> bf16 planes, fused deg zeroing ----------------
__global__ void splitx_zero_kernel(const float* __restrict__ x,
                                   __nv_bfloat16* __restrict__ A1,
                                   __nv_bfloat16* __restrict__ A2, int N) {
    int i = blockIdx.x * blockDim.x + threadIdx.x;
    if (i < N) d_deg[i] = 0;
    if (i >= N * 64) return;
    float2 v = ((const float2*)x)[i];
    __nv_bfloat16 h0 = __float2bfloat16(v.x);
    __nv_bfloat16 h1 = __float2bfloat16(v.y);
    __nv_bfloat162 hi; hi.x = h0; hi.y = h1;
    __nv_bfloat162 lo;
    lo.x = __float2bfloat16(v.x - __bfloat162float(h0));
    lo.y = __float2bfloat16(v.y - __bfloat162float(h1));
    ((__nv_bfloat162*)A1)[i] = hi;
    ((__nv_bfloat162*)A2)[i] = lo;
}

__global__ void detect_kernel(const unsigned int* w) {
    int t = threadIdx.x;
    unsigned v = w[2 * t + 1];
    unsigned m = __ballot_sync(0xffffffffu, v != 0u);
    if (t == 0) d_e64 = (m == 0u) ? 1 : 0;
}

__global__ void hist_kernel(const void* ei, int E) {
    int i = blockIdx.x * blockDim.x + threadIdx.x;
    int e = 2 * i;
    if (e >= E) return;
    bool vec = ((E & 1) == 0) && (e + 1 < E);
    int dA, dB = -1;
    if (d_e64) {
        const long long* p = (const long long*)ei;
        if (vec) { longlong2 dv = *(const longlong2*)&p[(size_t)E + e]; dA = (int)dv.x; dB = (int)dv.y; }
        else { dA = (int)p[(size_t)E + e]; if (e + 1 < E) dB = (int)p[(size_t)E + e + 1]; }
    } else {
        const int* p = (const int*)ei;
        if (vec) { int2 dv = *(const int2*)&p[(size_t)E + e]; dA = dv.x; dB = dv.y; }
        else { dA = p[(size_t)E + e]; if (e + 1 < E) dB = p[(size_t)E + e + 1]; }
    }
    atomicAdd(&d_deg[dA], 1);
    if (dB >= 0) atomicAdd(&d_deg[dB], 1);
}

__global__ void degsum_kernel(int n) {
    __shared__ int sh[256];
    int t = threadIdx.x;
    int i = blockIdx.x * 256 + t;
    sh[t] = (i < n) ? d_deg[i] : 0;
    __syncthreads();
    for (int s = 128; s > 0; s >>= 1) {
        if (t < s) sh[t] += sh[t + s];
        __syncthreads();
    }
    if (t == 0) d_bsum[blockIdx.x] = sh[0];
}

__global__ void bscan_kernel(int G) {
    __shared__ int sh[256];
    int t = threadIdx.x;
    int v = (t < G) ? d_bsum[t] : 0;
    sh[t] = v;
    __syncthreads();
    for (int s = 1; s < 256; s <<= 1) {
        int add = (t >= s) ? sh[t - s] : 0;
        __syncthreads();
        sh[t] += add;
        __syncthreads();
    }
    d_boff[t] = sh[t] - v;
}

__global__ void offsets_kernel(int n) {
    __shared__ int sh[256];
    int t = threadIdx.x;
    int i = blockIdx.x * 256 + t;
    int v = (i < n) ? d_deg[i] : 0;
    sh[t] = v;
    __syncthreads();
    for (int s = 1; s < 256; s <<= 1) {
        int add = (t >= s) ? sh[t - s] : 0;
        __syncthreads();
        sh[t] += add;
        __syncthreads();
    }
    if (i < n) {
        int excl = d_boff[blockIdx.x] + sh[t] - v;
        d_off[i] = excl;
        d_cur[i] = excl;
        d_invdeg[i] = 1.0f / (float)((v > 1) ? v : 1);
    }
}

__global__ void csrfill_kernel(const void* ei, int E) {
    int i = blockIdx.x * blockDim.x + threadIdx.x;
    int e = 2 * i;
    if (e >= E) return;
    bool vec = ((E & 1) == 0) && (e + 1 < E);
    int sA, dA, sB = -1, dB = -1;
    if (d_e64) {
        const long long* p = (const long long*)ei;
        if (vec) {
            longlong2 sv = *(const longlong2*)&p[e];
            longlong2 dv = *(const longlong2*)&p[(size_t)E + e];
            sA = (int)sv.x; sB = (int)sv.y; dA = (int)dv.x; dB = (int)dv.y;
        } else {
            sA = (int)p[e]; dA = (int)p[(size_t)E + e];
            if (e + 1 < E) { sB = (int)p[e + 1]; dB = (int)p[(size_t)E + e + 1]; }
        }
    } else {
        const int* p = (const int*)ei;
        if (vec) {
            int2 sv = *(const int2*)&p[e];
            int2 dv = *(const int2*)&p[(size_t)E + e];
            sA = sv.x; sB = sv.y; dA = dv.x; dB = dv.y;
        } else {
            sA = p[e]; dA = p[(size_t)E + e];
            if (e + 1 < E) { sB = p[e + 1]; dB = p[(size_t)E + e + 1]; }
        }
    }
    int pa = atomicAdd(&d_cur[dA], 1);
    d_csr[pa] = sA;
    if (dB >= 0) {
        int pb = atomicAdd(&d_cur[dB], 1);
        d_csr[pb] = sB;
    }
}

// ---------------- fused weight prep ----------------
__global__ void prep_all_kernel(
        const float* __restrict__ Wl0, const float* __restrict__ bl0,
        const float* __restrict__ Wr0, const float* __restrict__ Ws0, const float* __restrict__ bs0,
        const float* __restrict__ Wl1, const float* __restrict__ bl1,
        const float* __restrict__ Wr1, const float* __restrict__ Ws1, const float* __restrict__ bs1,
        const float* __restrict__ Wl2, const float* __restrict__ bl2,
        const float* __restrict__ Wr2, const float* __restrict__ Ws2, const float* __restrict__ bs2,
        __nv_bfloat16* __restrict__ W1t0p, __nv_bfloat16* __restrict__ W2t0p,
        __nv_bfloat16* __restrict__ W1t1p, __nv_bfloat16* __restrict__ W2t1p,
        __nv_bfloat16* __restrict__ W1t2p, __nv_bfloat16* __restrict__ W2t2p,
        float* __restrict__ bias0p, float* __restrict__ bias1p, float* __restrict__ bias2p) {
    int L = blockIdx.y;
    const float *Wl, *bl, *Wr, *Ws, *bs;
    __nv_bfloat16 *W1t, *W2t;
    float* bias;
    int dout;
    if (L == 0) { Wl = Wl0; bl = bl0; Wr = Wr0; Ws = Ws0; bs = bs0; W1t = W1t0p; W2t = W2t0p; bias = bias0p; dout = 128; }
    else if (L == 1) { Wl = Wl1; bl = bl1; Wr = Wr1; Ws = Ws1; bs = bs1; W1t = W1t1p; W2t = W2t1p; bias = bias1p; dout = 128; }
    else { Wl = Wl2; bl = bl2; Wr = Wr2; Ws = Ws2; bs = bs2; W1t = W1t2p; W2t = W2t2p; bias = bias2p; dout = 64; }

    int idx = blockIdx.x * blockDim.x + threadIdx.x;
    int tot = 128 * dout;
    if (idx < tot) {
        int k = idx / dout, c = idx % dout;
        float v  = Wl[idx];
        float v2 = Wr[idx] + Ws[idx];
        __nv_bfloat16 h1 = __float2bfloat16(v);
        __nv_bfloat16 h2 = __float2bfloat16(v - __bfloat162float(h1));
        W1t[(size_t)c * 128 + k] = h1;
        W2t[(size_t)c * 128 + k] = h2;
        __nv_bfloat16 g1 = __float2bfloat16(v2);
        __nv_bfloat16 g2 = __float2bfloat16(v2 - __bfloat162float(g1));
        W1t[(size_t)(dout + c) * 128 + k] = g1;
        W2t[(size_t)(dout + c) * 128 + k] = g2;
    }
    if (idx < dout) bias[idx] = bl[idx] + bs[idx];
}

// ---------------- pure-streaming bf16-split tensor-core GEMM ----------------
#define GBM 128
#define RSTR 12   // u32/row: 8 data + 4 pad; frag banks (12g+t)%32 distinct

__device__ __forceinline__ void cp16(uint32_t dst, const void* src) {
    asm volatile("cp.async.cg.shared.global [%0], [%1], 16;" :: "r"(dst), "l"(src));
}
__device__ __forceinline__ void mma_bf16(float* c, const uint32_t* a, const uint32_t* b) {
    asm volatile(
        "mma.sync.aligned.m16n8k16.row.col.f32.bf16.bf16.f32 "
        "{%0,%1,%2,%3}, {%4,%5,%6,%7}, {%8,%9}, {%0,%1,%2,%3};"
        : "+f"(c[0]), "+f"(c[1]), "+f"(c[2]), "+f"(c[3])
        : "r"(a[0]), "r"(a[1]), "r"(a[2]), "r"(a[3]), "r"(b[0]), "r"(b[1]));
}

__global__ __launch_bounds__(256, 2) void gemm_bf16_kernel(
        const __nv_bfloat16* __restrict__ A1g,
        const __nv_bfloat16* __restrict__ A2g,
        const __nv_bfloat16* __restrict__ W1t,
        const __nv_bfloat16* __restrict__ W2t,
        __half* __restrict__ Y, float* __restrict__ Z,
        int Nrows, int ycols) {
    __shared__ uint32_t SA1[2][128 * RSTR];
    __shared__ uint32_t SA2[2][128 * RSTR];
    __shared__ uint32_t SB1[2][128 * RSTR];
    __shared__ uint32_t SB2[2][128 * RSTR];

    const int tid = threadIdx.x;
    const int warp = tid >> 5, lane = tid & 31;
    const int g = lane >> 2, t = lane & 3;
    const int wr = warp >> 2, wc = warp & 3;
    const int blockRow = blockIdx.x * GBM;
    const int blockCol = blockIdx.y * 128;

    float acc[4][4][4];
#pragma unroll
    for (int mt = 0; mt < 4; mt++)
#pragma unroll
        for (int nt = 0; nt < 4; nt++)
#pragma unroll
            for (int i = 0; i < 4; i++) acc[mt][nt][i] = 0.0f;

    const int row = tid >> 1;
    const int h8 = (tid & 1) * 8;
    const uint32_t soff = (row * RSTR + (tid & 1) * 4) * 4;
    uint32_t da1[2] = { (uint32_t)__cvta_generic_to_shared(&SA1[0][0]) + soff,
                        (uint32_t)__cvta_generic_to_shared(&SA1[1][0]) + soff };
    uint32_t da2[2] = { (uint32_t)__cvta_generic_to_shared(&SA2[0][0]) + soff,
                        (uint32_t)__cvta_generic_to_shared(&SA2[1][0]) + soff };
    uint32_t db1[2] = { (uint32_t)__cvta_generic_to_shared(&SB1[0][0]) + soff,
                        (uint32_t)__cvta_generic_to_shared(&SB1[1][0]) + soff };
    uint32_t db2[2] = { (uint32_t)__cvta_generic_to_shared(&SB2[0][0]) + soff,
                        (uint32_t)__cvta_generic_to_shared(&SB2[1][0]) + soff };

    const __nv_bfloat16* a1src = A1g + (size_t)(blockRow + row) * 128 + h8;
    const __nv_bfloat16* a2src = A2g + (size_t)(blockRow + row) * 128 + h8;
    const __nv_bfloat16* b1src = W1t + (size_t)(blockCol + row) * 128 + h8;
    const __nv_bfloat16* b2src = W2t + (size_t)(blockCol + row) * 128 + h8;

    cp16(da1[0], a1src);
    cp16(da2[0], a2src);
    cp16(db1[0], b1src);
    cp16(db2[0], b2src);
    asm volatile("cp.async.commit_group;");

#pragma unroll 1
    for (int s = 0; s < 8; s++) {
        const int buf = s & 1;
        asm volatile("cp.async.wait_group 0;");
        __syncthreads();     // single barrier per stage: also protects buffer reuse
        if (s < 7) {
            int k0 = (s + 1) * 16;
            cp16(da1[buf ^ 1], a1src + k0);
            cp16(da2[buf ^ 1], a2src + k0);
            cp16(db1[buf ^ 1], b1src + k0);
            cp16(db2[buf ^ 1], b2src + k0);
            asm volatile("cp.async.commit_group;");
        }

        uint32_t B1f[4][2], B2f[4][2];
        const uint32_t* __restrict__ Bp1 = SB1[buf];
        const uint32_t* __restrict__ Bp2 = SB2[buf];
#pragma unroll
        for (int nt = 0; nt < 4; nt++) {
            int n = (wc * 32 + nt * 8 + g) * RSTR;
            B1f[nt][0] = Bp1[n + t];
            B1f[nt][1] = Bp1[n + t + 4];
            B2f[nt][0] = Bp2[n + t];
            B2f[nt][1] = Bp2[n + t + 4];
        }
        const uint32_t* __restrict__ Ap1 = SA1[buf];
        const uint32_t* __restrict__ Ap2 = SA2[buf];
#pragma unroll
        for (int mt = 0; mt < 4; mt++) {
            uint32_t A1f[4], A2f[4];
            int r0 = (wr * 64 + mt * 16 + g) * RSTR;
            A1f[0] = Ap1[r0 + t];
            A1f[1] = Ap1[r0 + 8 * RSTR + t];
            A1f[2] = Ap1[r0 + t + 4];
            A1f[3] = Ap1[r0 + 8 * RSTR + t + 4];
            A2f[0] = Ap2[r0 + t];
            A2f[1] = Ap2[r0 + 8 * RSTR + t];
            A2f[2] = Ap2[r0 + t + 4];
            A2f[3] = Ap2[r0 + 8 * RSTR + t + 4];
            // three passes in separate nt-loops: consecutive mma hit different
            // accumulators (RAW reuse distance = 4 mma)
#pragma unroll
            for (int nt = 0; nt < 4; nt++) mma_bf16(acc[mt][nt], A1f, B1f[nt]);
#pragma unroll
            for (int nt = 0; nt < 4; nt++) mma_bf16(acc[mt][nt], A1f, B2f[nt]);
#pragma unroll
            for (int nt = 0; nt < 4; nt++) mma_bf16(acc[mt][nt], A2f, B1f[nt]);
        }
    }

    // epilogue
#pragma unroll
    for (int mt = 0; mt < 4; mt++) {
        int r0 = blockRow + wr * 64 + mt * 16 + g;
#pragma unroll
        for (int nt = 0; nt < 4; nt++) {
            int cg = blockCol + wc * 32 + nt * 8 + 2 * t;
            if (cg < ycols) {
                __half2 h0 = __floats2half2_rn(acc[mt][nt][0], acc[mt][nt][1]);
                __half2 h1 = __floats2half2_rn(acc[mt][nt][2], acc[mt][nt][3]);
                if (r0 < Nrows) *(__half2*)&Y[(size_t)r0 * ycols + cg] = h0;
                if (r0 + 8 < Nrows) *(__half2*)&Y[(size_t)(r0 + 8) * ycols + cg] = h1;
            } else {
                int cz = cg - ycols;
                if (r0 < Nrows)
                    *(float2*)&Z[(size_t)r0 * ycols + cz] = make_float2(acc[mt][nt][0], acc[mt][nt][1]);
                if (r0 + 8 < Nrows)
                    *(float2*)&Z[(size_t)(r0 + 8) * ycols + cz] = make_float2(acc[mt][nt][2], acc[mt][nt][3]);
            }
        }
    }
}

// ---------------- aggregation: warp per node; hidden layers emit split-bf16 planes ----------------
template <int DOUT, bool SPLIT>
__global__ void agg_kernel(const __half* __restrict__ Y, const float* __restrict__ Z,
                           const float* __restrict__ bias,
                           float* __restrict__ outp,
                           __nv_bfloat16* __restrict__ P1, __nv_bfloat16* __restrict__ P2,
                           int N, int applyRelu) {
    int warp = (blockIdx.x * blockDim.x + threadIdx.x) >> 5;
    int lane = threadIdx.x & 31;
    if (warp >= N) return;
    int node = warp;
    int beg = d_off[node];
    int end = beg + d_deg[node];
    float inv = d_invdeg[node];

    if (DOUT == 128) {
        const uint2* __restrict__ yp = (const uint2*)Y;
        float4 acc = make_float4(0.f, 0.f, 0.f, 0.f);
        int p = beg;
        for (; p + 4 <= end; p += 4) {
            int s0 = d_csr[p + 0], s1 = d_csr[p + 1], s2 = d_csr[p + 2], s3 = d_csr[p + 3];
            uint2 u0 = yp[(size_t)s0 * 32 + lane];
            uint2 u1 = yp[(size_t)s1 * 32 + lane];
            uint2 u2 = yp[(size_t)s2 * 32 + lane];
            uint2 u3 = yp[(size_t)s3 * 32 + lane];
            float2 a0 = __half22float2(*(__half2*)&u0.x), b0 = __half22float2(*(__half2*)&u0.y);
            float2 a1 = __half22float2(*(__half2*)&u1.x), b1 = __half22float2(*(__half2*)&u1.y);
            float2 a2 = __half22float2(*(__half2*)&u2.x), b2 = __half22float2(*(__half2*)&u2.y);
            float2 a3 = __half22float2(*(__half2*)&u3.x), b3 = __half22float2(*(__half2*)&u3.y);
            acc.x += (a0.x + a1.x) + (a2.x + a3.x);
            acc.y += (a0.y + a1.y) + (a2.y + a3.y);
            acc.z += (b0.x + b1.x) + (b2.x + b3.x);
            acc.w += (b0.y + b1.y) + (b2.y + b3.y);
        }
        for (; p < end; ++p) {
            int s = d_csr[p];
            uint2 u = yp[(size_t)s * 32 + lane];
            float2 a = __half22float2(*(__half2*)&u.x), b = __half22float2(*(__half2*)&u.y);
            acc.x += a.x; acc.y += a.y; acc.z += b.x; acc.w += b.y;
        }
        float4 zz = ((const float4*)Z)[(size_t)node * 32 + lane];
        float4 b = ((const float4*)bias)[lane];
        float4 r;
        r.x = acc.x * inv + zz.x + b.x;
        r.y = acc.y * inv + zz.y + b.y;
        r.z = acc.z * inv + zz.z + b.z;
        r.w = acc.w * inv + zz.w + b.w;
        if (applyRelu) {
            r.x = fmaxf(r.x, 0.f); r.y = fmaxf(r.y, 0.f);
            r.z = fmaxf(r.z, 0.f); r.w = fmaxf(r.w, 0.f);
        }
        if (SPLIT) {
            __nv_bfloat16 hx = __float2bfloat16(r.x), hy = __float2bfloat16(r.y);
            __nv_bfloat16 hz = __float2bfloat16(r.z), hw = __float2bfloat16(r.w);
            __nv_bfloat162 hiA; hiA.x = hx; hiA.y = hy;
            __nv_bfloat162 hiB; hiB.x = hz; hiB.y = hw;
            __nv_bfloat162 loA;
            loA.x = __float2bfloat16(r.x - __bfloat162float(hx));
            loA.y = __float2bfloat16(r.y - __bfloat162float(hy));
            __nv_bfloat162 loB;
            loB.x = __float2bfloat16(r.z - __bfloat162float(hz));
            loB.y = __float2bfloat16(r.w - __bfloat162float(hw));
            uint2 w1 = make_uint2(*(uint32_t*)&hiA, *(uint32_t*)&hiB);
            uint2 w2 = make_uint2(*(uint32_t*)&loA, *(uint32_t*)&loB);
            ((uint2*)P1)[(size_t)node * 32 + lane] = w1;
            ((uint2*)P2)[(size_t)node * 32 + lane] = w2;
        } else {
            ((float4*)outp)[(size_t)node * 32 + lane] = r;
        }
    } else {  // DOUT == 64, final layer
        const uint32_t* __restrict__ yp = (const uint32_t*)Y;
        float2 acc = make_float2(0.f, 0.f);
        int p = beg;
        for (; p + 4 <= end; p += 4) {
            int s0 = d_csr[p + 0], s1 = d_csr[p + 1], s2 = d_csr[p + 2], s3 = d_csr[p + 3];
            uint32_t u0 = yp[(size_t)s0 * 32 + lane];
            uint32_t u1 = yp[(size_t)s1 * 32 + lane];
            uint32_t u2 = yp[(size_t)s2 * 32 + lane];
            uint32_t u3 = yp[(size_t)s3 * 32 + lane];
            float2 f0 = __half22float2(*(__half2*)&u0);
            float2 f1 = __half22float2(*(__half2*)&u1);
            float2 f2 = __half22float2(*(__half2*)&u2);
            float2 f3 = __half22float2(*(__half2*)&u3);
            acc.x += (f0.x + f1.x) + (f2.x + f3.x);
            acc.y += (f0.y + f1.y) + (f2.y + f3.y);
        }
        for (; p < end; ++p) {
            int s = d_csr[p];
            uint32_t u = yp[(size_t)s * 32 + lane];
            float2 f = __half22float2(*(__half2*)&u);
            acc.x += f.x; acc.y += f.y;
        }
        float2 zz = ((const float2*)Z)[(size_t)node * 32 + lane];
        float2 b = ((const float2*)bias)[lane];
        float2 r;
        r.x = acc.x * inv + zz.x + b.x;
        r.y = acc.y * inv + zz.y + b.y;
        if (applyRelu) { r.x = fmaxf(r.x, 0.f); r.y = fmaxf(r.y, 0.f); }
        ((float2*)outp)[(size_t)node * 32 + lane] = r;
    }
}

// ---------------- launch ----------------
extern "C" void kernel_launch(void* const* d_in, const int* in_sizes, int n_in,
                              void* d_out, int out_size) {
    const float* x  = (const float*)d_in[0];
    const void*  ei = d_in[1];
    const float* Wl0 = (const float*)d_in[4];
    const float* bl0 = (const float*)d_in[5];
    const float* Wr0 = (const float*)d_in[6];
    const float* Ws0 = (const float*)d_in[7];
    const float* bs0 = (const float*)d_in[8];
    const float* Wl1 = (const float*)d_in[9];
    const float* bl1 = (const float*)d_in[10];
    const float* Wr1 = (const float*)d_in[11];
    const float* Ws1 = (const float*)d_in[12];
    const float* bs1 = (const float*)d_in[13];
    const float* Wl2 = (const float*)d_in[14];
    const float* bl2 = (const float*)d_in[15];
    const float* Wr2 = (const float*)d_in[16];
    const float* Ws2 = (const float*)d_in[17];
    const float* bs2 = (const float*)d_in[18];

    int N = in_sizes[0] / 128;
    int E = in_sizes[3];

    __nv_bfloat16 *A1, *A2, *W10, *W20, *W11, *W21, *W12, *W22;
    __half* y16; float* z; float *b0, *b1, *b2;
    cudaGetSymbolAddress((void**)&A1,  d_A1);
    cudaGetSymbolAddress((void**)&A2,  d_A2);
    cudaGetSymbolAddress((void**)&y16, d_y16);
    cudaGetSymbolAddress((void**)&z,   d_z);
    cudaGetSymbolAddress((void**)&W10, d_W1t0);
    cudaGetSymbolAddress((void**)&W20, d_W2t0);
    cudaGetSymbolAddress((void**)&W11, d_W1t1);
    cudaGetSymbolAddress((void**)&W21, d_W2t1);
    cudaGetSymbolAddress((void**)&W12, d_W1t2);
    cudaGetSymbolAddress((void**)&W22, d_W2t2);
    cudaGetSymbolAddress((void**)&b0, d_bias0);
    cudaGetSymbolAddress((void**)&b1, d_bias1);
    cudaGetSymbolAddress((void**)&b2, d_bias2);

    int aggBlocks = (N * 32 + 255) / 256;
    int pairBlocks = ((E + 1) / 2 + 255) / 256;
    int G = (N + 255) / 256;

    splitx_zero_kernel<<<(N * 64 + 255) / 256, 256>>>(x, A1, A2, N);
    detect_kernel<<<1, 32>>>((const unsigned int*)ei);
    {
        dim3 grid((128 * 128 + 255) / 256, 3);
        prep_all_kernel<<<grid, 256>>>(Wl0, bl0, Wr0, Ws0, bs0,
                                       Wl1, bl1, Wr1, Ws1, bs1,
                                       Wl2, bl2, Wr2, Ws2, bs2,
                                       W10, W20, W11, W21, W12, W22,
                                       b0, b1, b2);
    }
    // GEMM layer 0 (profiled slot #4)
    {
        dim3 grid((N + GBM - 1) / GBM, 2);
        gemm_bf16_kernel<<<grid, 256>>>(A1, A2, W10, W20, y16, z, N, 128);
    }
    hist_kernel<<<pairBlocks, 256>>>(ei, E);
    degsum_kernel<<<G, 256>>>(N);
    bscan_kernel<<<1, 256>>>(G);
    offsets_kernel<<<G, 256>>>(N);
    csrfill_kernel<<<pairBlocks, 256>>>(ei, E);
    agg_kernel<128, true><<<aggBlocks, 256>>>(y16, z, b0, nullptr, A1, A2, N, 1);
    {
        dim3 grid((N + GBM - 1) / GBM, 2);
        gemm_bf16_kernel<<<grid, 256>>>(A1, A2, W11, W21, y16, z, N, 128);
        agg_kernel<128, true><<<aggBlocks, 256>>>(y16, z, b1, nullptr, A1, A2, N, 1);
    }
    {
        dim3 grid((N + GBM - 1) / GBM, 1);
        gemm_bf16_kernel<<<grid, 256>>>(A1, A2, W12, W22, y16, z, N, 64);
        agg_kernel<64, false><<<aggBlocks, 256>>>(y16, z, b2, (float*)d_out, nullptr, nullptr, N, 0);
    }
}

// round 11
// speedup vs baseline: 1.5559x; 1.5559x over previous
#include <cuda_runtime.h>
#include <cuda_bf16.h>
#include <cuda_fp16.h>
#include <cstdint>

#define NMAX 50000
#define EMAX 800000

// ---------------- scratch ----------------
__device__ __align__(16) __half d_y16[NMAX * 128];   // aggregated-path GEMM output (fp16)
__device__ __align__(16) float  d_z[NMAX * 128];     // self-path GEMM output (fp32)
__device__ __align__(16) float  d_hA[NMAX * 128];
__device__ __align__(16) float  d_hB[NMAX * 128];
__device__ __align__(16) __nv_bfloat16 d_W1t0[256 * 128];
__device__ __align__(16) __nv_bfloat16 d_W2t0[256 * 128];
__device__ __align__(16) __nv_bfloat16 d_W1t1[256 * 128];
__device__ __align__(16) __nv_bfloat16 d_W2t1[256 * 128];
__device__ __align__(16) __nv_bfloat16 d_W1t2[128 * 128];
__device__ __align__(16) __nv_bfloat16 d_W2t2[128 * 128];
__device__ __align__(16) float d_bias0[256];
__device__ __align__(16) float d_bias1[256];
__device__ __align__(16) float d_bias2[128];
__device__ int   d_deg[NMAX];
__device__ int   d_off[NMAX];
__device__ int   d_cur[NMAX];
__device__ float d_invdeg[NMAX];
__device__ int   d_csr[EMAX];
__device__ int   d_bsum[256];
__device__ int   d_boff[256];
__device__ int   d_e64;

// ---------------- CSR build ----------------
__global__ void zero_deg_kernel(int n) {
    int i = blockIdx.x * blockDim.x + threadIdx.x;
    if (i < n) d_deg[i] = 0;
}

__global__ void detect_kernel(const unsigned int* w) {
    int t = threadIdx.x;
    unsigned v = w[2 * t + 1];
    unsigned m = __ballot_sync(0xffffffffu, v != 0u);
    if (t == 0) d_e64 = (m == 0u) ? 1 : 0;
}

__global__ void hist_kernel(const void* ei, int E) {
    int i = blockIdx.x * blockDim.x + threadIdx.x;
    int e = 2 * i;
    if (e >= E) return;
    bool vec = ((E & 1) == 0) && (e + 1 < E);
    int dA, dB = -1;
    if (d_e64) {
        const long long* p = (const long long*)ei;
        if (vec) { longlong2 dv = *(const longlong2*)&p[(size_t)E + e]; dA = (int)dv.x; dB = (int)dv.y; }
        else { dA = (int)p[(size_t)E + e]; if (e + 1 < E) dB = (int)p[(size_t)E + e + 1]; }
    } else {
        const int* p = (const int*)ei;
        if (vec) { int2 dv = *(const int2*)&p[(size_t)E + e]; dA = dv.x; dB = dv.y; }
        else { dA = p[(size_t)E + e]; if (e + 1 < E) dB = p[(size_t)E + e + 1]; }
    }
    atomicAdd(&d_deg[dA], 1);
    if (dB >= 0) atomicAdd(&d_deg[dB], 1);
}

__global__ void degsum_kernel(int n) {
    __shared__ int sh[256];
    int t = threadIdx.x;
    int i = blockIdx.x * 256 + t;
    sh[t] = (i < n) ? d_deg[i] : 0;
    __syncthreads();
    for (int s = 128; s > 0; s >>= 1) {
        if (t < s) sh[t] += sh[t + s];
        __syncthreads();
    }
    if (t == 0) d_bsum[blockIdx.x] = sh[0];
}

__global__ void bscan_kernel(int G) {
    __shared__ int sh[256];
    int t = threadIdx.x;
    int v = (t < G) ? d_bsum[t] : 0;
    sh[t] = v;
    __syncthreads();
    for (int s = 1; s < 256; s <<= 1) {
        int add = (t >= s) ? sh[t - s] : 0;
        __syncthreads();
        sh[t] += add;
        __syncthreads();
    }
    d_boff[t] = sh[t] - v;
}

__global__ void offsets_kernel(int n) {
    __shared__ int sh[256];
    int t = threadIdx.x;
    int i = blockIdx.x * 256 + t;
    int v = (i < n) ? d_deg[i] : 0;
    sh[t] = v;
    __syncthreads();
    for (int s = 1; s < 256; s <<= 1) {
        int add = (t >= s) ? sh[t - s] : 0;
        __syncthreads();
        sh[t] += add;
        __syncthreads();
    }
    if (i < n) {
        int excl = d_boff[blockIdx.x] + sh[t] - v;
        d_off[i] = excl;
        d_cur[i] = excl;
        d_invdeg[i] = 1.0f / (float)((v > 1) ? v : 1);
    }
}

__global__ void csrfill_kernel(const void* ei, int E) {
    int i = blockIdx.x * blockDim.x + threadIdx.x;
    int e = 2 * i;
    if (e >= E) return;
    bool vec = ((E & 1) == 0) && (e + 1 < E);
    int sA, dA, sB = -1, dB = -1;
    if (d_e64) {
        const long long* p = (const long long*)ei;
        if (vec) {
            longlong2 sv = *(const longlong2*)&p[e];
            longlong2 dv = *(const longlong2*)&p[(size_t)E + e];
            sA = (int)sv.x; sB = (int)sv.y; dA = (int)dv.x; dB = (int)dv.y;
        } else {
            sA = (int)p[e]; dA = (int)p[(size_t)E + e];
            if (e + 1 < E) { sB = (int)p[e + 1]; dB = (int)p[(size_t)E + e + 1]; }
        }
    } else {
        const int* p = (const int*)ei;
        if (vec) {
            int2 sv = *(const int2*)&p[e];
            int2 dv = *(const int2*)&p[(size_t)E + e];
            sA = sv.x; sB = sv.y; dA = dv.x; dB = dv.y;
        } else {
            sA = p[e]; dA = p[(size_t)E + e];
            if (e + 1 < E) { sB = p[e + 1]; dB = p[(size_t)E + e + 1]; }
        }
    }
    int pa = atomicAdd(&d_cur[dA], 1);
    d_csr[pa] = sA;
    if (dB >= 0) {
        int pb = atomicAdd(&d_cur[dB], 1);
        d_csr[pb] = sB;
    }
}

// ---------------- fused weight prep: all 3 layers ----------------
__global__ void prep_all_kernel(
        const float* __restrict__ Wl0, const float* __restrict__ bl0,
        const float* __restrict__ Wr0, const float* __restrict__ Ws0, const float* __restrict__ bs0,
        const float* __restrict__ Wl1, const float* __restrict__ bl1,
        const float* __restrict__ Wr1, const float* __restrict__ Ws1, const float* __restrict__ bs1,
        const float* __restrict__ Wl2, const float* __restrict__ bl2,
        const float* __restrict__ Wr2, const float* __restrict__ Ws2, const float* __restrict__ bs2,
        __nv_bfloat16* __restrict__ W1t0p, __nv_bfloat16* __restrict__ W2t0p,
        __nv_bfloat16* __restrict__ W1t1p, __nv_bfloat16* __restrict__ W2t1p,
        __nv_bfloat16* __restrict__ W1t2p, __nv_bfloat16* __restrict__ W2t2p,
        float* __restrict__ bias0p, float* __restrict__ bias1p, float* __restrict__ bias2p) {
    int L = blockIdx.y;
    const float *Wl, *bl, *Wr, *Ws, *bs;
    __nv_bfloat16 *W1t, *W2t;
    float* bias;
    int dout;
    if (L == 0) { Wl = Wl0; bl = bl0; Wr = Wr0; Ws = Ws0; bs = bs0; W1t = W1t0p; W2t = W2t0p; bias = bias0p; dout = 128; }
    else if (L == 1) { Wl = Wl1; bl = bl1; Wr = Wr1; Ws = Ws1; bs = bs1; W1t = W1t1p; W2t = W2t1p; bias = bias1p; dout = 128; }
    else { Wl = Wl2; bl = bl2; Wr = Wr2; Ws = Ws2; bs = bs2; W1t = W1t2p; W2t = W2t2p; bias = bias2p; dout = 64; }

    int idx = blockIdx.x * blockDim.x + threadIdx.x;
    int tot = 128 * dout;
    if (idx < tot) {
        int k = idx / dout, c = idx % dout;
        float v  = Wl[idx];
        float v2 = Wr[idx] + Ws[idx];
        __nv_bfloat16 h1 = __float2bfloat16(v);
        __nv_bfloat16 h2 = __float2bfloat16(v - __bfloat162float(h1));
        W1t[(size_t)c * 128 + k] = h1;
        W2t[(size_t)c * 128 + k] = h2;
        __nv_bfloat16 g1 = __float2bfloat16(v2);
        __nv_bfloat16 g2 = __float2bfloat16(v2 - __bfloat162float(g1));
        W1t[(size_t)(dout + c) * 128 + k] = g1;
        W2t[(size_t)(dout + c) * 128 + k] = g2;
    }
    if (idx < dout) bias[idx] = bl[idx] + bs[idx];
}

// ---------------- bf16-split tensor-core GEMM (R7 formulation, unchanged) ----------------
#define GBM 128
#define RSTR 12

__device__ __forceinline__ void cp16(uint32_t dst, const void* src) {
    asm volatile("cp.async.cg.shared.global [%0], [%1], 16;" :: "r"(dst), "l"(src));
}
__device__ __forceinline__ void mma_bf16(float* c, const uint32_t* a, const uint32_t* b) {
    asm volatile(
        "mma.sync.aligned.m16n8k16.row.col.f32.bf16.bf16.f32 "
        "{%0,%1,%2,%3}, {%4,%5,%6,%7}, {%8,%9}, {%0,%1,%2,%3};"
        : "+f"(c[0]), "+f"(c[1]), "+f"(c[2]), "+f"(c[3])
        : "r"(a[0]), "r"(a[1]), "r"(a[2]), "r"(a[3]), "r"(b[0]), "r"(b[1]));
}
__device__ __forceinline__ uint32_t pack_split1(float x, float y) {
    __nv_bfloat162 h = __floats2bfloat162_rn(x, y);
    return *(uint32_t*)&h;
}

__global__ __launch_bounds__(256, 2) void gemm_bf16_kernel(
        const float* __restrict__ A,
        const __nv_bfloat16* __restrict__ W1t,
        const __nv_bfloat16* __restrict__ W2t,
        __half* __restrict__ Y, float* __restrict__ Z,
        int Nrows, int ycols) {
    __shared__ uint32_t As1[128 * RSTR];
    __shared__ uint32_t As2[128 * RSTR];
    __shared__ uint32_t Bs1[2][128 * RSTR];
    __shared__ uint32_t Bs2[2][128 * RSTR];

    const int tid = threadIdx.x;
    const int warp = tid >> 5, lane = tid & 31;
    const int g = lane >> 2, t = lane & 3;
    const int wr = warp >> 2, wc = warp & 3;
    const int blockRow = blockIdx.x * GBM;
    const int blockCol = blockIdx.y * 128;

    float acc[4][4][4];
#pragma unroll
    for (int mt = 0; mt < 4; mt++)
#pragma unroll
        for (int nt = 0; nt < 4; nt++)
#pragma unroll
            for (int i = 0; i < 4; i++) acc[mt][nt][i] = 0.0f;

    int arow[2], akq[2];
#pragma unroll
    for (int q = 0; q < 2; q++) {
        int lin = tid + 256 * q;
        arow[q] = lin >> 2;
        akq[q]  = (lin & 3) * 4;
    }
    const int bn = tid >> 1;
    const int bkh = (tid & 1) * 8;
    uint32_t b1base0 = __cvta_generic_to_shared(&Bs1[0][0]);
    uint32_t b1base1 = __cvta_generic_to_shared(&Bs1[1][0]);
    uint32_t b2base0 = __cvta_generic_to_shared(&Bs2[0][0]);
    uint32_t b2base1 = __cvta_generic_to_shared(&Bs2[1][0]);
    uint32_t bdst1[2] = { b1base0 + (bn * RSTR) * 4 + bkh * 2, b1base1 + (bn * RSTR) * 4 + bkh * 2 };
    uint32_t bdst2[2] = { b2base0 + (bn * RSTR) * 4 + bkh * 2, b2base1 + (bn * RSTR) * 4 + bkh * 2 };

    const float4 z4 = make_float4(0.f, 0.f, 0.f, 0.f);
    float4 ra[2];

    {
        const __nv_bfloat16* s1 = &W1t[(size_t)(blockCol + bn) * 128 + bkh];
        const __nv_bfloat16* s2 = &W2t[(size_t)(blockCol + bn) * 128 + bkh];
        cp16(bdst1[0], s1);
        cp16(bdst2[0], s2);
        asm volatile("cp.async.commit_group;");
    }
#pragma unroll
    for (int q = 0; q < 2; q++) {
        int gr = blockRow + arow[q];
        ra[q] = (gr < Nrows) ? *(const float4*)&A[(size_t)gr * 128 + akq[q]] : z4;
    }

#pragma unroll 1
    for (int s = 0; s < 8; s++) {
        const int buf = s & 1;
#pragma unroll
        for (int q = 0; q < 2; q++) {
            float4 v = ra[q];
            float h0 = __bfloat162float(__float2bfloat16(v.x));
            float h1 = __bfloat162float(__float2bfloat16(v.y));
            float h2 = __bfloat162float(__float2bfloat16(v.z));
            float h3 = __bfloat162float(__float2bfloat16(v.w));
            uint32_t p1a = pack_split1(v.x, v.y);
            uint32_t p1b = pack_split1(v.z, v.w);
            uint32_t p2a = pack_split1(v.x - h0, v.y - h1);
            uint32_t p2b = pack_split1(v.z - h2, v.w - h3);
            int u = arow[q] * RSTR + (akq[q] >> 1);
            *(uint2*)&As1[u] = make_uint2(p1a, p1b);
            *(uint2*)&As2[u] = make_uint2(p2a, p2b);
        }
        if (s < 7) {
            int k0 = (s + 1) * 16;
#pragma unroll
            for (int q = 0; q < 2; q++) {
                int gr = blockRow + arow[q];
                ra[q] = (gr < Nrows) ? *(const float4*)&A[(size_t)gr * 128 + k0 + akq[q]] : z4;
            }
            const __nv_bfloat16* s1 = &W1t[(size_t)(blockCol + bn) * 128 + k0 + bkh];
            const __nv_bfloat16* s2 = &W2t[(size_t)(blockCol + bn) * 128 + k0 + bkh];
            cp16(bdst1[buf ^ 1], s1);
            cp16(bdst2[buf ^ 1], s2);
            asm volatile("cp.async.commit_group;");
            asm volatile("cp.async.wait_group 1;");
        } else {
            asm volatile("cp.async.wait_group 0;");
        }
        __syncthreads();

        uint32_t B1f[4][2], B2f[4][2];
        const uint32_t* __restrict__ Bp1 = Bs1[buf];
        const uint32_t* __restrict__ Bp2 = Bs2[buf];
#pragma unroll
        for (int nt = 0; nt < 4; nt++) {
            int n = (wc * 32 + nt * 8 + g) * RSTR;
            B1f[nt][0] = Bp1[n + t];
            B1f[nt][1] = Bp1[n + t + 4];
            B2f[nt][0] = Bp2[n + t];
            B2f[nt][1] = Bp2[n + t + 4];
        }
#pragma unroll
        for (int mt = 0; mt < 4; mt++) {
            uint32_t A1f[4], A2f[4];
            int r0 = (wr * 64 + mt * 16 + g) * RSTR;
            A1f[0] = As1[r0 + t];
            A1f[1] = As1[r0 + 8 * RSTR + t];
            A1f[2] = As1[r0 + t + 4];
            A1f[3] = As1[r0 + 8 * RSTR + t + 4];
            A2f[0] = As2[r0 + t];
            A2f[1] = As2[r0 + 8 * RSTR + t];
            A2f[2] = As2[r0 + t + 4];
            A2f[3] = As2[r0 + 8 * RSTR + t + 4];
#pragma unroll
            for (int nt = 0; nt < 4; nt++) {
                mma_bf16(acc[mt][nt], A1f, B1f[nt]);
                mma_bf16(acc[mt][nt], A1f, B2f[nt]);
                mma_bf16(acc[mt][nt], A2f, B1f[nt]);
            }
        }
        __syncthreads();
    }

    // epilogue: y-cols -> fp16 plane, z-cols -> fp32 plane
#pragma unroll
    for (int mt = 0; mt < 4; mt++) {
        int r0 = blockRow + wr * 64 + mt * 16 + g;
#pragma unroll
        for (int nt = 0; nt < 4; nt++) {
            int cg = blockCol + wc * 32 + nt * 8 + 2 * t;
            if (cg < ycols) {
                __half2 h0 = __floats2half2_rn(acc[mt][nt][0], acc[mt][nt][1]);
                __half2 h1 = __floats2half2_rn(acc[mt][nt][2], acc[mt][nt][3]);
                if (r0 < Nrows) *(__half2*)&Y[(size_t)r0 * ycols + cg] = h0;
                if (r0 + 8 < Nrows) *(__half2*)&Y[(size_t)(r0 + 8) * ycols + cg] = h1;
            } else {
                int cz = cg - ycols;
                if (r0 < Nrows)
                    *(float2*)&Z[(size_t)r0 * ycols + cz] = make_float2(acc[mt][nt][0], acc[mt][nt][1]);
                if (r0 + 8 < Nrows)
                    *(float2*)&Z[(size_t)(r0 + 8) * ycols + cz] = make_float2(acc[mt][nt][2], acc[mt][nt][3]);
            }
        }
    }
}

// ---------------- aggregation: warp per node, fp16 y gathers ----------------
template <int DOUT>
__global__ void agg_kernel(const __half* __restrict__ Y, const float* __restrict__ Z,
                           const float* __restrict__ bias, float* __restrict__ outp,
                           int N, int applyRelu) {
    int warp = (blockIdx.x * blockDim.x + threadIdx.x) >> 5;
    int lane = threadIdx.x & 31;
    if (warp >= N) return;
    int node = warp;
    int beg = d_off[node];
    int end = beg + d_deg[node];
    float inv = d_invdeg[node];

    if (DOUT == 128) {
        const uint2* __restrict__ yp = (const uint2*)Y;
        float4 acc = make_float4(0.f, 0.f, 0.f, 0.f);
        int p = beg;
        for (; p + 4 <= end; p += 4) {
            int s0 = d_csr[p + 0], s1 = d_csr[p + 1], s2 = d_csr[p + 2], s3 = d_csr[p + 3];
            uint2 u0 = yp[(size_t)s0 * 32 + lane];
            uint2 u1 = yp[(size_t)s1 * 32 + lane];
            uint2 u2 = yp[(size_t)s2 * 32 + lane];
            uint2 u3 = yp[(size_t)s3 * 32 + lane];
            float2 a0 = __half22float2(*(__half2*)&u0.x), b0 = __half22float2(*(__half2*)&u0.y);
            float2 a1 = __half22float2(*(__half2*)&u1.x), b1 = __half22float2(*(__half2*)&u1.y);
            float2 a2 = __half22float2(*(__half2*)&u2.x), b2 = __half22float2(*(__half2*)&u2.y);
            float2 a3 = __half22float2(*(__half2*)&u3.x), b3 = __half22float2(*(__half2*)&u3.y);
            acc.x += (a0.x + a1.x) + (a2.x + a3.x);
            acc.y += (a0.y + a1.y) + (a2.y + a3.y);
            acc.z += (b0.x + b1.x) + (b2.x + b3.x);
            acc.w += (b0.y + b1.y) + (b2.y + b3.y);
        }
        for (; p < end; ++p) {
            int s = d_csr[p];
            uint2 u = yp[(size_t)s * 32 + lane];
            float2 a = __half22float2(*(__half2*)&u.x), b = __half22float2(*(__half2*)&u.y);
            acc.x += a.x; acc.y += a.y; acc.z += b.x; acc.w += b.y;
        }
        float4 zz = ((const float4*)Z)[(size_t)node * 32 + lane];
        float4 b = ((const float4*)bias)[lane];
        float4 r;
        r.x = acc.x * inv + zz.x + b.x;
        r.y = acc.y * inv + zz.y + b.y;
        r.z = acc.z * inv + zz.z + b.z;
        r.w = acc.w * inv + zz.w + b.w;
        if (applyRelu) {
            r.x = fmaxf(r.x, 0.f); r.y = fmaxf(r.y, 0.f);
            r.z = fmaxf(r.z, 0.f); r.w = fmaxf(r.w, 0.f);
        }
        ((float4*)outp)[(size_t)node * 32 + lane] = r;
    } else {  // DOUT == 64
        const uint32_t* __restrict__ yp = (const uint32_t*)Y;
        float2 acc = make_float2(0.f, 0.f);
        int p = beg;
        for (; p + 4 <= end; p += 4) {
            int s0 = d_csr[p + 0], s1 = d_csr[p + 1], s2 = d_csr[p + 2], s3 = d_csr[p + 3];
            uint32_t u0 = yp[(size_t)s0 * 32 + lane];
            uint32_t u1 = yp[(size_t)s1 * 32 + lane];
            uint32_t u2 = yp[(size_t)s2 * 32 + lane];
            uint32_t u3 = yp[(size_t)s3 * 32 + lane];
            float2 f0 = __half22float2(*(__half2*)&u0);
            float2 f1 = __half22float2(*(__half2*)&u1);
            float2 f2 = __half22float2(*(__half2*)&u2);
            float2 f3 = __half22float2(*(__half2*)&u3);
            acc.x += (f0.x + f1.x) + (f2.x + f3.x);
            acc.y += (f0.y + f1.y) + (f2.y + f3.y);
        }
        for (; p < end; ++p) {
            int s = d_csr[p];
            uint32_t u = yp[(size_t)s * 32 + lane];
            float2 f = __half22float2(*(__half2*)&u);
            acc.x += f.x; acc.y += f.y;
        }
        float2 zz = ((const float2*)Z)[(size_t)node * 32 + lane];
        float2 b = ((const float2*)bias)[lane];
        float2 r;
        r.x = acc.x * inv + zz.x + b.x;
        r.y = acc.y * inv + zz.y + b.y;
        if (applyRelu) { r.x = fmaxf(r.x, 0.f); r.y = fmaxf(r.y, 0.f); }
        ((float2*)outp)[(size_t)node * 32 + lane] = r;
    }
}

// ---------------- launch: fork CSR build onto a side stream, overlap with prep+gemm0 ----------------
extern "C" void kernel_launch(void* const* d_in, const int* in_sizes, int n_in,
                              void* d_out, int out_size) {
    const float* x  = (const float*)d_in[0];
    const void*  ei = d_in[1];
    const float* Wl0 = (const float*)d_in[4];
    const float* bl0 = (const float*)d_in[5];
    const float* Wr0 = (const float*)d_in[6];
    const float* Ws0 = (const float*)d_in[7];
    const float* bs0 = (const float*)d_in[8];
    const float* Wl1 = (const float*)d_in[9];
    const float* bl1 = (const float*)d_in[10];
    const float* Wr1 = (const float*)d_in[11];
    const float* Ws1 = (const float*)d_in[12];
    const float* bs1 = (const float*)d_in[13];
    const float* Wl2 = (const float*)d_in[14];
    const float* bl2 = (const float*)d_in[15];
    const float* Wr2 = (const float*)d_in[16];
    const float* Ws2 = (const float*)d_in[17];
    const float* bs2 = (const float*)d_in[18];

    int N = in_sizes[0] / 128;
    int E = in_sizes[3];

    __half* y16; float* z; float* hA; float* hB;
    __nv_bfloat16 *W10, *W20, *W11, *W21, *W12, *W22;
    float *b0, *b1, *b2;
    cudaGetSymbolAddress((void**)&y16, d_y16);
    cudaGetSymbolAddress((void**)&z,   d_z);
    cudaGetSymbolAddress((void**)&hA,  d_hA);
    cudaGetSymbolAddress((void**)&hB,  d_hB);
    cudaGetSymbolAddress((void**)&W10, d_W1t0);
    cudaGetSymbolAddress((void**)&W20, d_W2t0);
    cudaGetSymbolAddress((void**)&W11, d_W1t1);
    cudaGetSymbolAddress((void**)&W21, d_W2t1);
    cudaGetSymbolAddress((void**)&W12, d_W1t2);
    cudaGetSymbolAddress((void**)&W22, d_W2t2);
    cudaGetSymbolAddress((void**)&b0, d_bias0);
    cudaGetSymbolAddress((void**)&b1, d_bias1);
    cudaGetSymbolAddress((void**)&b2, d_bias2);

    int aggBlocks = (N * 32 + 255) / 256;
    int pairBlocks = ((E + 1) / 2 + 255) / 256;
    int G = (N + 255) / 256;
    dim3 prepGrid((128 * 128 + 255) / 256, 3);
    dim3 gemmGrid2((N + GBM - 1) / GBM, 2);
    dim3 gemmGrid1((N + GBM - 1) / GBM, 1);

    // one-time side-stream setup (first call is the uncaptured correctness run)
    static int inited = 0;
    static int streamsOK = 0;
    static cudaStream_t sCSR;
    static cudaEvent_t evFork, evCSR;
    if (!inited) {
        inited = 1;
        streamsOK =
            (cudaStreamCreateWithFlags(&sCSR, cudaStreamNonBlocking) == cudaSuccess) &&
            (cudaEventCreateWithFlags(&evFork, cudaEventDisableTiming) == cudaSuccess) &&
            (cudaEventCreateWithFlags(&evCSR,  cudaEventDisableTiming) == cudaSuccess);
    }

    if (streamsOK) {
        // fork: CSR chain on side stream, concurrent with prep + gemm0
        cudaEventRecord(evFork, 0);
        cudaStreamWaitEvent(sCSR, evFork, 0);
        zero_deg_kernel<<<G, 256, 0, sCSR>>>(N);
        detect_kernel<<<1, 32, 0, sCSR>>>((const unsigned int*)ei);
        hist_kernel<<<pairBlocks, 256, 0, sCSR>>>(ei, E);
        degsum_kernel<<<G, 256, 0, sCSR>>>(N);
        bscan_kernel<<<1, 256, 0, sCSR>>>(G);
        offsets_kernel<<<G, 256, 0, sCSR>>>(N);
        csrfill_kernel<<<pairBlocks, 256, 0, sCSR>>>(ei, E);
        cudaEventRecord(evCSR, sCSR);

        prep_all_kernel<<<prepGrid, 256>>>(Wl0, bl0, Wr0, Ws0, bs0,
                                           Wl1, bl1, Wr1, Ws1, bs1,
                                           Wl2, bl2, Wr2, Ws2, bs2,
                                           W10, W20, W11, W21, W12, W22,
                                           b0, b1, b2);
        gemm_bf16_kernel<<<gemmGrid2, 256>>>(x, W10, W20, y16, z, N, 128);

        // join: aggregation needs the CSR
        cudaStreamWaitEvent(0, evCSR, 0);
        agg_kernel<128><<<aggBlocks, 256>>>(y16, z, b0, hA, N, 1);
        gemm_bf16_kernel<<<gemmGrid2, 256>>>(hA, W11, W21, y16, z, N, 128);
        agg_kernel<128><<<aggBlocks, 256>>>(y16, z, b1, hB, N, 1);
        gemm_bf16_kernel<<<gemmGrid1, 256>>>(hB, W12, W22, y16, z, N, 64);
        agg_kernel<64><<<aggBlocks, 256>>>(y16, z, b2, (float*)d_out, N, 0);
    } else {
        // sequential fallback (identical to R7)
        zero_deg_kernel<<<G, 256>>>(N);
        detect_kernel<<<1, 32>>>((const unsigned int*)ei);
        prep_all_kernel<<<prepGrid, 256>>>(Wl0, bl0, Wr0, Ws0, bs0,
                                           Wl1, bl1, Wr1, Ws1, bs1,
                                           Wl2, bl2, Wr2, Ws2, bs2,
                                           W10, W20, W11, W21, W12, W22,
                                           b0, b1, b2);
        gemm_bf16_kernel<<<gemmGrid2, 256>>>(x, W10, W20, y16, z, N, 128);
        hist_kernel<<<pairBlocks, 256>>>(ei, E);
        degsum_kernel<<<G, 256>>>(N);
        bscan_kernel<<<1, 256>>>(G);
        offsets_kernel<<<G, 256>>>(N);
        csrfill_kernel<<<pairBlocks, 256>>>(ei, E);
        agg_kernel<128><<<aggBlocks, 256>>>(y16, z, b0, hA, N, 1);
        gemm_bf16_kernel<<<gemmGrid2, 256>>>(hA, W11, W21, y16, z, N, 128);
        agg_kernel<128><<<aggBlocks, 256>>>(y16, z, b1, hB, N, 1);
        gemm_bf16_kernel<<<gemmGrid1, 256>>>(hB, W12, W22, y16, z, N, 64);
        agg_kernel<64><<<aggBlocks, 256>>>(y16, z, b2, (float*)d_out, N, 0);
    }
}

// round 13
// speedup vs baseline: 1.8190x; 1.1690x over previous
#include <cuda_runtime.h>
#include <cuda_bf16.h>
#include <cuda_fp16.h>
#include <cstdint>

#define NMAX 50000
#define EMAX 800000

// ---------------- scratch ----------------
__device__ __align__(16) __half d_y16[NMAX * 128];   // aggregated-path GEMM output (fp16)
__device__ __align__(16) float  d_z[NMAX * 128];     // self-path GEMM output (fp32)
__device__ __align__(16) float  d_hA[NMAX * 128];
__device__ __align__(16) float  d_hB[NMAX * 128];
__device__ __align__(16) __half d_W1t0[256 * 128];
__device__ __align__(16) __half d_W2t0[256 * 128];
__device__ __align__(16) __half d_W1t1[256 * 128];
__device__ __align__(16) __half d_W2t1[256 * 128];
__device__ __align__(16) __half d_W1t2[128 * 128];
__device__ __align__(16) __half d_W2t2[128 * 128];
__device__ __align__(16) float d_bias0[256];
__device__ __align__(16) float d_bias1[256];
__device__ __align__(16) float d_bias2[128];
__device__ int   d_deg[NMAX];
__device__ int   d_off[NMAX];
__device__ int   d_cur[NMAX];
__device__ float d_invdeg[NMAX];
__device__ int   d_csr[EMAX];
__device__ int   d_bsum[256];
__device__ int   d_boff[256];
__device__ int   d_e64;

// ---------------- CSR build ----------------
__global__ void zero_deg_kernel(int n) {
    int i = blockIdx.x * blockDim.x + threadIdx.x;
    if (i < n) d_deg[i] = 0;
}

__global__ void detect_kernel(const unsigned int* w) {
    int t = threadIdx.x;
    unsigned v = w[2 * t + 1];
    unsigned m = __ballot_sync(0xffffffffu, v != 0u);
    if (t == 0) d_e64 = (m == 0u) ? 1 : 0;
}

__global__ void hist_kernel(const void* ei, int E) {
    int i = blockIdx.x * blockDim.x + threadIdx.x;
    int e = 2 * i;
    if (e >= E) return;
    bool vec = ((E & 1) == 0) && (e + 1 < E);
    int dA, dB = -1;
    if (d_e64) {
        const long long* p = (const long long*)ei;
        if (vec) { longlong2 dv = *(const longlong2*)&p[(size_t)E + e]; dA = (int)dv.x; dB = (int)dv.y; }
        else { dA = (int)p[(size_t)E + e]; if (e + 1 < E) dB = (int)p[(size_t)E + e + 1]; }
    } else {
        const int* p = (const int*)ei;
        if (vec) { int2 dv = *(const int2*)&p[(size_t)E + e]; dA = dv.x; dB = dv.y; }
        else { dA = p[(size_t)E + e]; if (e + 1 < E) dB = p[(size_t)E + e + 1]; }
    }
    atomicAdd(&d_deg[dA], 1);
    if (dB >= 0) atomicAdd(&d_deg[dB], 1);
}

__global__ void degsum_kernel(int n) {
    __shared__ int sh[256];
    int t = threadIdx.x;
    int i = blockIdx.x * 256 + t;
    sh[t] = (i < n) ? d_deg[i] : 0;
    __syncthreads();
    for (int s = 128; s > 0; s >>= 1) {
        if (t < s) sh[t] += sh[t + s];
        __syncthreads();
    }
    if (t == 0) d_bsum[blockIdx.x] = sh[0];
}

__global__ void bscan_kernel(int G) {
    __shared__ int sh[256];
    int t = threadIdx.x;
    int v = (t < G) ? d_bsum[t] : 0;
    sh[t] = v;
    __syncthreads();
    for (int s = 1; s < 256; s <<= 1) {
        int add = (t >= s) ? sh[t - s] : 0;
        __syncthreads();
        sh[t] += add;
        __syncthreads();
    }
    d_boff[t] = sh[t] - v;
}

__global__ void offsets_kernel(int n) {
    __shared__ int sh[256];
    int t = threadIdx.x;
    int i = blockIdx.x * 256 + t;
    int v = (i < n) ? d_deg[i] : 0;
    sh[t] = v;
    __syncthreads();
    for (int s = 1; s < 256; s <<= 1) {
        int add = (t >= s) ? sh[t - s] : 0;
        __syncthreads();
        sh[t] += add;
        __syncthreads();
    }
    if (i < n) {
        int excl = d_boff[blockIdx.x] + sh[t] - v;
        d_off[i] = excl;
        d_cur[i] = excl;
        d_invdeg[i] = 1.0f / (float)((v > 1) ? v : 1);
    }
}

__global__ void csrfill_kernel(const void* ei, int E) {
    int i = blockIdx.x * blockDim.x + threadIdx.x;
    int e = 2 * i;
    if (e >= E) return;
    bool vec = ((E & 1) == 0) && (e + 1 < E);
    int sA, dA, sB = -1, dB = -1;
    if (d_e64) {
        const long long* p = (const long long*)ei;
        if (vec) {
            longlong2 sv = *(const longlong2*)&p[e];
            longlong2 dv = *(const longlong2*)&p[(size_t)E + e];
            sA = (int)sv.x; sB = (int)sv.y; dA = (int)dv.x; dB = (int)dv.y;
        } else {
            sA = (int)p[e]; dA = (int)p[(size_t)E + e];
            if (e + 1 < E) { sB = (int)p[e + 1]; dB = (int)p[(size_t)E + e + 1]; }
        }
    } else {
        const int* p = (const int*)ei;
        if (vec) {
            int2 sv = *(const int2*)&p[e];
            int2 dv = *(const int2*)&p[(size_t)E + e];
            sA = sv.x; sB = sv.y; dA = dv.x; dB = dv.y;
        } else {
            sA = p[e]; dA = p[(size_t)E + e];
            if (e + 1 < E) { sB = p[e + 1]; dB = p[(size_t)E + e + 1]; }
        }
    }
    int pa = atomicAdd(&d_cur[dA], 1);
    d_csr[pa] = sA;
    if (dB >= 0) {
        int pb = atomicAdd(&d_cur[dB], 1);
        d_csr[pb] = sB;
    }
}

// ---------------- fused weight prep: all 3 layers, fp16 hi/lo split ----------------
__global__ void prep_all_kernel(
        const float* __restrict__ Wl0, const float* __restrict__ bl0,
        const float* __restrict__ Wr0, const float* __restrict__ Ws0, const float* __restrict__ bs0,
        const float* __restrict__ Wl1, const float* __restrict__ bl1,
        const float* __restrict__ Wr1, const float* __restrict__ Ws1, const float* __restrict__ bs1,
        const float* __restrict__ Wl2, const float* __restrict__ bl2,
        const float* __restrict__ Wr2, const float* __restrict__ Ws2, const float* __restrict__ bs2,
        __half* __restrict__ W1t0p, __half* __restrict__ W2t0p,
        __half* __restrict__ W1t1p, __half* __restrict__ W2t1p,
        __half* __restrict__ W1t2p, __half* __restrict__ W2t2p,
        float* __restrict__ bias0p, float* __restrict__ bias1p, float* __restrict__ bias2p) {
    int L = blockIdx.y;
    const float *Wl, *bl, *Wr, *Ws, *bs;
    __half *W1t, *W2t;
    float* bias;
    int dout;
    if (L == 0) { Wl = Wl0; bl = bl0; Wr = Wr0; Ws = Ws0; bs = bs0; W1t = W1t0p; W2t = W2t0p; bias = bias0p; dout = 128; }
    else if (L == 1) { Wl = Wl1; bl = bl1; Wr = Wr1; Ws = Ws1; bs = bs1; W1t = W1t1p; W2t = W2t1p; bias = bias1p; dout = 128; }
    else { Wl = Wl2; bl = bl2; Wr = Wr2; Ws = Ws2; bs = bs2; W1t = W1t2p; W2t = W2t2p; bias = bias2p; dout = 64; }

    int idx = blockIdx.x * blockDim.x + threadIdx.x;
    int tot = 128 * dout;
    if (idx < tot) {
        int k = idx / dout, c = idx % dout;
        float v  = Wl[idx];
        float v2 = Wr[idx] + Ws[idx];
        __half h1 = __float2half_rn(v);
        __half h2 = __float2half_rn(v - __half2float(h1));
        W1t[(size_t)c * 128 + k] = h1;
        W2t[(size_t)c * 128 + k] = h2;
        __half g1 = __float2half_rn(v2);
        __half g2 = __float2half_rn(v2 - __half2float(g1));
        W1t[(size_t)(dout + c) * 128 + k] = g1;
        W2t[(size_t)(dout + c) * 128 + k] = g2;
    }
    if (idx < dout) bias[idx] = bl[idx] + bs[idx];
}

// ---------------- fp16 2-pass tensor-core GEMM (R7 loop skeleton) ----------------
#define GBM 128
#define RSTR 12

__device__ __forceinline__ void cp16(uint32_t dst, const void* src) {
    asm volatile("cp.async.cg.shared.global [%0], [%1], 16;" :: "r"(dst), "l"(src));
}
__device__ __forceinline__ void mma_fp16(float* c, const uint32_t* a, const uint32_t* b) {
    asm volatile(
        "mma.sync.aligned.m16n8k16.row.col.f32.f16.f16.f32 "
        "{%0,%1,%2,%3}, {%4,%5,%6,%7}, {%8,%9}, {%0,%1,%2,%3};"
        : "+f"(c[0]), "+f"(c[1]), "+f"(c[2]), "+f"(c[3])
        : "r"(a[0]), "r"(a[1]), "r"(a[2]), "r"(a[3]), "r"(b[0]), "r"(b[1]));
}

__global__ __launch_bounds__(256, 2) void gemm_fp16_kernel(
        const float* __restrict__ A,
        const __half* __restrict__ W1t,
        const __half* __restrict__ W2t,
        __half* __restrict__ Y, float* __restrict__ Z,
        int Nrows, int ycols) {
    __shared__ uint32_t As1[128 * RSTR];
    __shared__ uint32_t Bs1[2][128 * RSTR];
    __shared__ uint32_t Bs2[2][128 * RSTR];

    const int tid = threadIdx.x;
    const int warp = tid >> 5, lane = tid & 31;
    const int g = lane >> 2, t = lane & 3;
    const int wr = warp >> 2, wc = warp & 3;
    const int blockRow = blockIdx.x * GBM;
    const int blockCol = blockIdx.y * 128;

    float acc[4][4][4];
#pragma unroll
    for (int mt = 0; mt < 4; mt++)
#pragma unroll
        for (int nt = 0; nt < 4; nt++)
#pragma unroll
            for (int i = 0; i < 4; i++) acc[mt][nt][i] = 0.0f;

    int arow[2], akq[2];
#pragma unroll
    for (int q = 0; q < 2; q++) {
        int lin = tid + 256 * q;
        arow[q] = lin >> 2;
        akq[q]  = (lin & 3) * 4;
    }
    const int bn = tid >> 1;
    const int bkh = (tid & 1) * 8;
    uint32_t b1base0 = __cvta_generic_to_shared(&Bs1[0][0]);
    uint32_t b1base1 = __cvta_generic_to_shared(&Bs1[1][0]);
    uint32_t b2base0 = __cvta_generic_to_shared(&Bs2[0][0]);
    uint32_t b2base1 = __cvta_generic_to_shared(&Bs2[1][0]);
    uint32_t bdst1[2] = { b1base0 + (bn * RSTR) * 4 + bkh * 2, b1base1 + (bn * RSTR) * 4 + bkh * 2 };
    uint32_t bdst2[2] = { b2base0 + (bn * RSTR) * 4 + bkh * 2, b2base1 + (bn * RSTR) * 4 + bkh * 2 };

    const float4 z4 = make_float4(0.f, 0.f, 0.f, 0.f);
    float4 ra[2];

    {
        const __half* s1 = &W1t[(size_t)(blockCol + bn) * 128 + bkh];
        const __half* s2 = &W2t[(size_t)(blockCol + bn) * 128 + bkh];
        cp16(bdst1[0], s1);
        cp16(bdst2[0], s2);
        asm volatile("cp.async.commit_group;");
    }
#pragma unroll
    for (int q = 0; q < 2; q++) {
        int gr = blockRow + arow[q];
        ra[q] = (gr < Nrows) ? *(const float4*)&A[(size_t)gr * 128 + akq[q]] : z4;
    }

#pragma unroll 1
    for (int s = 0; s < 8; s++) {
        const int buf = s & 1;
        // store A regs -> smem (single fp16 plane)
#pragma unroll
        for (int q = 0; q < 2; q++) {
            float4 v = ra[q];
            __half2 p0 = __floats2half2_rn(v.x, v.y);
            __half2 p1 = __floats2half2_rn(v.z, v.w);
            int u = arow[q] * RSTR + (akq[q] >> 1);
            *(uint2*)&As1[u] = make_uint2(*(uint32_t*)&p0, *(uint32_t*)&p1);
        }
        if (s < 7) {
            int k0 = (s + 1) * 16;
#pragma unroll
            for (int q = 0; q < 2; q++) {
                int gr = blockRow + arow[q];
                ra[q] = (gr < Nrows) ? *(const float4*)&A[(size_t)gr * 128 + k0 + akq[q]] : z4;
            }
            const __half* s1 = &W1t[(size_t)(blockCol + bn) * 128 + k0 + bkh];
            const __half* s2 = &W2t[(size_t)(blockCol + bn) * 128 + k0 + bkh];
            cp16(bdst1[buf ^ 1], s1);
            cp16(bdst2[buf ^ 1], s2);
            asm volatile("cp.async.commit_group;");
            asm volatile("cp.async.wait_group 1;");
        } else {
            asm volatile("cp.async.wait_group 0;");
        }
        __syncthreads();

        uint32_t B1f[4][2], B2f[4][2];
        const uint32_t* __restrict__ Bp1 = Bs1[buf];
        const uint32_t* __restrict__ Bp2 = Bs2[buf];
#pragma unroll
        for (int nt = 0; nt < 4; nt++) {
            int n = (wc * 32 + nt * 8 + g) * RSTR;
            B1f[nt][0] = Bp1[n + t];
            B1f[nt][1] = Bp1[n + t + 4];
            B2f[nt][0] = Bp2[n + t];
            B2f[nt][1] = Bp2[n + t + 4];
        }
#pragma unroll
        for (int mt = 0; mt < 4; mt++) {
            uint32_t A1f[4];
            int r0 = (wr * 64 + mt * 16 + g) * RSTR;
            A1f[0] = As1[r0 + t];
            A1f[1] = As1[r0 + 8 * RSTR + t];
            A1f[2] = As1[r0 + t + 4];
            A1f[3] = As1[r0 + 8 * RSTR + t + 4];
#pragma unroll
            for (int nt = 0; nt < 4; nt++) {
                mma_fp16(acc[mt][nt], A1f, B1f[nt]);
                mma_fp16(acc[mt][nt], A1f, B2f[nt]);
            }
        }
        __syncthreads();
    }

    // epilogue: y-cols -> fp16 plane, z-cols -> fp32 plane
#pragma unroll
    for (int mt = 0; mt < 4; mt++) {
        int r0 = blockRow + wr * 64 + mt * 16 + g;
#pragma unroll
        for (int nt = 0; nt < 4; nt++) {
            int cg = blockCol + wc * 32 + nt * 8 + 2 * t;
            if (cg < ycols) {
                __half2 h0 = __floats2half2_rn(acc[mt][nt][0], acc[mt][nt][1]);
                __half2 h1 = __floats2half2_rn(acc[mt][nt][2], acc[mt][nt][3]);
                if (r0 < Nrows) *(__half2*)&Y[(size_t)r0 * ycols + cg] = h0;
                if (r0 + 8 < Nrows) *(__half2*)&Y[(size_t)(r0 + 8) * ycols + cg] = h1;
            } else {
                int cz = cg - ycols;
                if (r0 < Nrows)
                    *(float2*)&Z[(size_t)r0 * ycols + cz] = make_float2(acc[mt][nt][0], acc[mt][nt][1]);
                if (r0 + 8 < Nrows)
                    *(float2*)&Z[(size_t)(r0 + 8) * ycols + cz] = make_float2(acc[mt][nt][2], acc[mt][nt][3]);
            }
        }
    }
}

// ---------------- aggregation: warp per node, fp16 y gathers ----------------
template <int DOUT>
__global__ void agg_kernel(const __half* __restrict__ Y, const float* __restrict__ Z,
                           const float* __restrict__ bias, float* __restrict__ outp,
                           int N, int applyRelu) {
    int warp = (blockIdx.x * blockDim.x + threadIdx.x) >> 5;
    int lane = threadIdx.x & 31;
    if (warp >= N) return;
    int node = warp;
    int beg = d_off[node];
    int end = beg + d_deg[node];
    float inv = d_invdeg[node];

    if (DOUT == 128) {
        const uint2* __restrict__ yp = (const uint2*)Y;
        float4 acc = make_float4(0.f, 0.f, 0.f, 0.f);
        int p = beg;
        for (; p + 4 <= end; p += 4) {
            int s0 = d_csr[p + 0], s1 = d_csr[p + 1], s2 = d_csr[p + 2], s3 = d_csr[p + 3];
            uint2 u0 = yp[(size_t)s0 * 32 + lane];
            uint2 u1 = yp[(size_t)s1 * 32 + lane];
            uint2 u2 = yp[(size_t)s2 * 32 + lane];
            uint2 u3 = yp[(size_t)s3 * 32 + lane];
            float2 a0 = __half22float2(*(__half2*)&u0.x), b0 = __half22float2(*(__half2*)&u0.y);
            float2 a1 = __half22float2(*(__half2*)&u1.x), b1 = __half22float2(*(__half2*)&u1.y);
            float2 a2 = __half22float2(*(__half2*)&u2.x), b2 = __half22float2(*(__half2*)&u2.y);
            float2 a3 = __half22float2(*(__half2*)&u3.x), b3 = __half22float2(*(__half2*)&u3.y);
            acc.x += (a0.x + a1.x) + (a2.x + a3.x);
            acc.y += (a0.y + a1.y) + (a2.y + a3.y);
            acc.z += (b0.x + b1.x) + (b2.x + b3.x);
            acc.w += (b0.y + b1.y) + (b2.y + b3.y);
        }
        for (; p < end; ++p) {
            int s = d_csr[p];
            uint2 u = yp[(size_t)s * 32 + lane];
            float2 a = __half22float2(*(__half2*)&u.x), b = __half22float2(*(__half2*)&u.y);
            acc.x += a.x; acc.y += a.y; acc.z += b.x; acc.w += b.y;
        }
        float4 zz = ((const float4*)Z)[(size_t)node * 32 + lane];
        float4 b = ((const float4*)bias)[lane];
        float4 r;
        r.x = acc.x * inv + zz.x + b.x;
        r.y = acc.y * inv + zz.y + b.y;
        r.z = acc.z * inv + zz.z + b.z;
        r.w = acc.w * inv + zz.w + b.w;
        if (applyRelu) {
            r.x = fmaxf(r.x, 0.f); r.y = fmaxf(r.y, 0.f);
            r.z = fmaxf(r.z, 0.f); r.w = fmaxf(r.w, 0.f);
        }
        ((float4*)outp)[(size_t)node * 32 + lane] = r;
    } else {  // DOUT == 64
        const uint32_t* __restrict__ yp = (const uint32_t*)Y;
        float2 acc = make_float2(0.f, 0.f);
        int p = beg;
        for (; p + 4 <= end; p += 4) {
            int s0 = d_csr[p + 0], s1 = d_csr[p + 1], s2 = d_csr[p + 2], s3 = d_csr[p + 3];
            uint32_t u0 = yp[(size_t)s0 * 32 + lane];
            uint32_t u1 = yp[(size_t)s1 * 32 + lane];
            uint32_t u2 = yp[(size_t)s2 * 32 + lane];
            uint32_t u3 = yp[(size_t)s3 * 32 + lane];
            float2 f0 = __half22float2(*(__half2*)&u0);
            float2 f1 = __half22float2(*(__half2*)&u1);
            float2 f2 = __half22float2(*(__half2*)&u2);
            float2 f3 = __half22float2(*(__half2*)&u3);
            acc.x += (f0.x + f1.x) + (f2.x + f3.x);
            acc.y += (f0.y + f1.y) + (f2.y + f3.y);
        }
        for (; p < end; ++p) {
            int s = d_csr[p];
            uint32_t u = yp[(size_t)s * 32 + lane];
            float2 f = __half22float2(*(__half2*)&u);
            acc.x += f.x; acc.y += f.y;
        }
        float2 zz = ((const float2*)Z)[(size_t)node * 32 + lane];
        float2 b = ((const float2*)bias)[lane];
        float2 r;
        r.x = acc.x * inv + zz.x + b.x;
        r.y = acc.y * inv + zz.y + b.y;
        if (applyRelu) { r.x = fmaxf(r.x, 0.f); r.y = fmaxf(r.y, 0.f); }
        ((float2*)outp)[(size_t)node * 32 + lane] = r;
    }
}

// ---------------- launch: fork CSR build onto a side stream, overlap with prep+gemm0 ----------------
extern "C" void kernel_launch(void* const* d_in, const int* in_sizes, int n_in,
                              void* d_out, int out_size) {
    const float* x  = (const float*)d_in[0];
    const void*  ei = d_in[1];
    const float* Wl0 = (const float*)d_in[4];
    const float* bl0 = (const float*)d_in[5];
    const float* Wr0 = (const float*)d_in[6];
    const float* Ws0 = (const float*)d_in[7];
    const float* bs0 = (const float*)d_in[8];
    const float* Wl1 = (const float*)d_in[9];
    const float* bl1 = (const float*)d_in[10];
    const float* Wr1 = (const float*)d_in[11];
    const float* Ws1 = (const float*)d_in[12];
    const float* bs1 = (const float*)d_in[13];
    const float* Wl2 = (const float*)d_in[14];
    const float* bl2 = (const float*)d_in[15];
    const float* Wr2 = (const float*)d_in[16];
    const float* Ws2 = (const float*)d_in[17];
    const float* bs2 = (const float*)d_in[18];

    int N = in_sizes[0] / 128;
    int E = in_sizes[3];

    __half* y16; float* z; float* hA; float* hB;
    __half *W10, *W20, *W11, *W21, *W12, *W22;
    float *b0, *b1, *b2;
    cudaGetSymbolAddress((void**)&y16, d_y16);
    cudaGetSymbolAddress((void**)&z,   d_z);
    cudaGetSymbolAddress((void**)&hA,  d_hA);
    cudaGetSymbolAddress((void**)&hB,  d_hB);
    cudaGetSymbolAddress((void**)&W10, d_W1t0);
    cudaGetSymbolAddress((void**)&W20, d_W2t0);
    cudaGetSymbolAddress((void**)&W11, d_W1t1);
    cudaGetSymbolAddress((void**)&W21, d_W2t1);
    cudaGetSymbolAddress((void**)&W12, d_W1t2);
    cudaGetSymbolAddress((void**)&W22, d_W2t2);
    cudaGetSymbolAddress((void**)&b0, d_bias0);
    cudaGetSymbolAddress((void**)&b1, d_bias1);
    cudaGetSymbolAddress((void**)&b2, d_bias2);

    int aggBlocks = (N * 32 + 255) / 256;
    int pairBlocks = ((E + 1) / 2 + 255) / 256;
    int G = (N + 255) / 256;
    dim3 prepGrid((128 * 128 + 255) / 256, 3);
    dim3 gemmGrid2((N + GBM - 1) / GBM, 2);
    dim3 gemmGrid1((N + GBM - 1) / GBM, 1);

    static int inited = 0;
    static int streamsOK = 0;
    static cudaStream_t sCSR;
    static cudaEvent_t evFork, evCSR;
    if (!inited) {
        inited = 1;
        streamsOK =
            (cudaStreamCreateWithFlags(&sCSR, cudaStreamNonBlocking) == cudaSuccess) &&
            (cudaEventCreateWithFlags(&evFork, cudaEventDisableTiming) == cudaSuccess) &&
            (cudaEventCreateWithFlags(&evCSR,  cudaEventDisableTiming) == cudaSuccess);
    }

    if (streamsOK) {
        cudaEventRecord(evFork, 0);
        cudaStreamWaitEvent(sCSR, evFork, 0);
        zero_deg_kernel<<<G, 256, 0, sCSR>>>(N);
        detect_kernel<<<1, 32, 0, sCSR>>>((const unsigned int*)ei);
        hist_kernel<<<pairBlocks, 256, 0, sCSR>>>(ei, E);
        degsum_kernel<<<G, 256, 0, sCSR>>>(N);
        bscan_kernel<<<1, 256, 0, sCSR>>>(G);
        offsets_kernel<<<G, 256, 0, sCSR>>>(N);
        csrfill_kernel<<<pairBlocks, 256, 0, sCSR>>>(ei, E);
        cudaEventRecord(evCSR, sCSR);

        prep_all_kernel<<<prepGrid, 256>>>(Wl0, bl0, Wr0, Ws0, bs0,
                                           Wl1, bl1, Wr1, Ws1, bs1,
                                           Wl2, bl2, Wr2, Ws2, bs2,
                                           W10, W20, W11, W21, W12, W22,
                                           b0, b1, b2);
        gemm_fp16_kernel<<<gemmGrid2, 256>>>(x, W10, W20, y16, z, N, 128);

        cudaStreamWaitEvent(0, evCSR, 0);
        agg_kernel<128><<<aggBlocks, 256>>>(y16, z, b0, hA, N, 1);
        gemm_fp16_kernel<<<gemmGrid2, 256>>>(hA, W11, W21, y16, z, N, 128);
        agg_kernel<128><<<aggBlocks, 256>>>(y16, z, b1, hB, N, 1);
        gemm_fp16_kernel<<<gemmGrid1, 256>>>(hB, W12, W22, y16, z, N, 64);
        agg_kernel<64><<<aggBlocks, 256>>>(y16, z, b2, (float*)d_out, N, 0);
    } else {
        zero_deg_kernel<<<G, 256>>>(N);
        detect_kernel<<<1, 32>>>((const unsigned int*)ei);
        prep_all_kernel<<<prepGrid, 256>>>(Wl0, bl0, Wr0, Ws0, bs0,
                                           Wl1, bl1, Wr1, Ws1, bs1,
                                           Wl2, bl2, Wr2, Ws2, bs2,
                                           W10, W20, W11, W21, W12, W22,
                                           b0, b1, b2);
        gemm_fp16_kernel<<<gemmGrid2, 256>>>(x, W10, W20, y16, z, N, 128);
        hist_kernel<<<pairBlocks, 256>>>(ei, E);
        degsum_kernel<<<G, 256>>>(N);
        bscan_kernel<<<1, 256>>>(G);
        offsets_kernel<<<G, 256>>>(N);
        csrfill_kernel<<<pairBlocks, 256>>>(ei, E);
        agg_kernel<128><<<aggBlocks, 256>>>(y16, z, b0, hA, N, 1);
        gemm_fp16_kernel<<<gemmGrid2, 256>>>(hA, W11, W21, y16, z, N, 128);
        agg_kernel<128><<<aggBlocks, 256>>>(y16, z, b1, hB, N, 1);
        gemm_fp16_kernel<<<gemmGrid1, 256>>>(hB, W12, W22, y16, z, N, 64);
        agg_kernel<64><<<aggBlocks, 256>>>(y16, z, b2, (float*)d_out, N, 0);
    }
}